// round 9
// baseline (speedup 1.0000x reference)
#include <cuda_runtime.h>
#include <cuda_bf16.h>
#include <cuda_fp16.h>
#include <cstdint>

#define DIM 128
#define NMAX 100000
#define EMAX 600000
#define CSR_BLOCKS 148
#define CSR_THREADS 1024

// ---------------- scratch (device globals; no allocations allowed) ----------------
__device__ float g_deg[NMAX];
__device__ float g_dinv[NMAX];
__device__ __align__(16) __half g_h[(size_t)NMAX * DIM];   // h in fp16 -> L2-resident
__device__ int  g_cnt[NMAX];
__device__ int  g_off[NMAX];
__device__ int  g_fill[NMAX];
__device__ int  g_chunksum[CSR_BLOCKS];
__device__ int  g_barcnt;
__device__ int2 g_edges[EMAX];                 // (src row, norm bits) grouped by dst
__device__ __nv_bfloat16 g_Wt_hi[DIM * DIM];   // W transposed: [n][k], bf16 hi part
__device__ __nv_bfloat16 g_Wt_lo[DIM * DIM];   // bf16 lo part (residual)

// ---------------- launch 1: zero deg/cnt/barrier + split W ----------------
__global__ void initwsplit_kernel(const float* __restrict__ W, int N) {
    int i = blockIdx.x * blockDim.x + threadIdx.x;
    if (i < N) { g_deg[i] = 0.0f; g_cnt[i] = 0; }
    if (i == 0) g_barcnt = 0;
    if (i < DIM * DIM) {
        int k = i >> 7, n = i & 127;
        float v = W[i];
        __nv_bfloat16 hi = __float2bfloat16(v);
        g_Wt_hi[n * DIM + k] = hi;
        g_Wt_lo[n * DIM + k] = __float2bfloat16(v - __bfloat162float(hi));
    }
}

// ---------------- grid-wide software barrier (all CSR blocks resident) ----------------
__device__ __forceinline__ void grid_barrier(int target) {
    __syncthreads();
    if (threadIdx.x == 0) {
        __threadfence();
        atomicAdd(&g_barcnt, 1);
        while (*(volatile int*)&g_barcnt < target) __nanosleep(64);
    }
    __syncthreads();
    __threadfence();
}

// ---------------- launch 3: fused deg -> dinv+scan -> fill (persistent, 1 block/SM) ----------------
__global__ __launch_bounds__(CSR_THREADS, 1) void csr_kernel(
    const int* __restrict__ ei, const float* __restrict__ ew, int N, int E)
{
    const int t = threadIdx.x;
    const int gtid = blockIdx.x * CSR_THREADS + t;
    const int gstride = CSR_BLOCKS * CSR_THREADS;

    // ---- phase 1: degree + in-count ----
    for (int e = gtid; e < E; e += gstride) {
        int c = ei[E + e];
        atomicAdd(&g_deg[c], ew[e]);
        atomicAdd(&g_cnt[c], 1);
    }
    grid_barrier(CSR_BLOCKS);

    // ---- phase 2: dinv + exclusive scan of g_cnt ----
    for (int i = gtid; i < N; i += gstride) {
        float d = g_deg[i];
        g_dinv[i] = (d > 0.0f) ? rsqrtf(d) : 0.0f;
    }

    const int chunk = (N + CSR_BLOCKS - 1) / CSR_BLOCKS;   // 676
    const int base = blockIdx.x * chunk;
    const int len = min(chunk, N - base);                   // may be <=0 for last blocks

    __shared__ int wsum[32];
    int lane = t & 31, wid = t >> 5;
    int v = (len > 0 && t < len) ? g_cnt[base + t] : 0;
    int s = v;
    #pragma unroll
    for (int o = 1; o < 32; o <<= 1) {
        int u = __shfl_up_sync(0xffffffffu, s, o);
        if (lane >= o) s += u;
    }
    if (lane == 31) wsum[wid] = s;
    __syncthreads();
    if (wid == 0) {
        int ws = wsum[lane];
        int p = ws;
        #pragma unroll
        for (int o = 1; o < 32; o <<= 1) {
            int u = __shfl_up_sync(0xffffffffu, p, o);
            if (lane >= o) p += u;
        }
        wsum[lane] = p - ws;   // exclusive warp offsets
    }
    __syncthreads();
    int excl = s - v + wsum[wid];
    if (t == CSR_THREADS - 1) g_chunksum[blockIdx.x] = excl + v;
    grid_barrier(2 * CSR_BLOCKS);

    // cross-chunk prefix: sum of chunksums of blocks < blockIdx.x
    __shared__ int psh[256];
    int pv = (t < blockIdx.x) ? g_chunksum[t] : 0;         // blockIdx.x <= 147 < 256
    if (t < 256) psh[t] = pv;
    __syncthreads();
    if (t < 256) {
        #pragma unroll
        for (int o = 128; o > 0; o >>= 1) {
            if (t < o) psh[t] += psh[t + o];
            __syncthreads();
        }
    } else {
        #pragma unroll
        for (int o = 128; o > 0; o >>= 1) __syncthreads();
    }
    int prefix = psh[0];
    if (len > 0 && t < len) {
        int o = excl + prefix;
        g_off[base + t] = o;
        g_fill[base + t] = o;
    }
    grid_barrier(3 * CSR_BLOCKS);

    // ---- phase 3: fill CSR edge records ----
    for (int e = gtid; e < E; e += gstride) {
        int r = ei[e];
        int c = ei[E + e];
        float nrm = g_dinv[r] * ew[e] * g_dinv[c];
        int p = atomicAdd(&g_fill[c], 1);
        g_edges[p] = make_int2(r, __float_as_int(nrm));
    }
}

// ---------------- GEMM: h = x @ W  (bf16 3-term split on tensor cores) ----------------
__device__ __forceinline__ void mma16816(float* c, const uint32_t* a, uint32_t b0, uint32_t b1) {
    asm volatile(
        "mma.sync.aligned.m16n8k16.row.col.f32.bf16.bf16.f32 "
        "{%0,%1,%2,%3}, {%4,%5,%6,%7}, {%8,%9}, {%0,%1,%2,%3};"
        : "+f"(c[0]), "+f"(c[1]), "+f"(c[2]), "+f"(c[3])
        : "r"(a[0]), "r"(a[1]), "r"(a[2]), "r"(a[3]), "r"(b0), "r"(b1));
}

#define LDA 136  // 128 + 8 bf16 pad -> conflict-free fragment loads

__global__ __launch_bounds__(256) void gemm_kernel(const float* __restrict__ x, int N) {
    __shared__ __nv_bfloat16 As_hi[64 * LDA];
    __shared__ __nv_bfloat16 As_lo[64 * LDA];

    const int tid = threadIdx.x;
    const int row0 = blockIdx.x * 64;

    #pragma unroll
    for (int idx = tid; idx < 64 * DIM; idx += 256) {
        int r = idx >> 7, k = idx & 127;
        float v = (row0 + r < N) ? __ldcs(&x[(size_t)(row0 + r) * DIM + k]) : 0.0f;
        __nv_bfloat16 hi = __float2bfloat16(v);
        As_hi[r * LDA + k] = hi;
        As_lo[r * LDA + k] = __float2bfloat16(v - __bfloat162float(hi));
    }
    __syncthreads();

    const int warp = tid >> 5, lane = tid & 31;
    const int wm = warp >> 2, wn = warp & 3;
    const int g = lane >> 2, c = lane & 3;

    float acc[2][4][4];
    #pragma unroll
    for (int i = 0; i < 2; i++)
        #pragma unroll
        for (int j = 0; j < 4; j++)
            #pragma unroll
            for (int q = 0; q < 4; q++) acc[i][j][q] = 0.0f;

    #pragma unroll
    for (int ks = 0; ks < 8; ks++) {
        const int kb = ks * 16;
        uint32_t ah[2][4], al[2][4];
        #pragma unroll
        for (int i = 0; i < 2; i++) {
            int r0 = wm * 32 + i * 16 + g;
            int col0 = kb + 2 * c;
            ah[i][0] = *(const uint32_t*)&As_hi[r0 * LDA + col0];
            ah[i][1] = *(const uint32_t*)&As_hi[(r0 + 8) * LDA + col0];
            ah[i][2] = *(const uint32_t*)&As_hi[r0 * LDA + col0 + 8];
            ah[i][3] = *(const uint32_t*)&As_hi[(r0 + 8) * LDA + col0 + 8];
            al[i][0] = *(const uint32_t*)&As_lo[r0 * LDA + col0];
            al[i][1] = *(const uint32_t*)&As_lo[(r0 + 8) * LDA + col0];
            al[i][2] = *(const uint32_t*)&As_lo[r0 * LDA + col0 + 8];
            al[i][3] = *(const uint32_t*)&As_lo[(r0 + 8) * LDA + col0 + 8];
        }
        #pragma unroll
        for (int j = 0; j < 4; j++) {
            int n0 = wn * 32 + j * 8 + g;
            uint32_t bh0 = *(const uint32_t*)&g_Wt_hi[n0 * DIM + kb + 2 * c];
            uint32_t bh1 = *(const uint32_t*)&g_Wt_hi[n0 * DIM + kb + 8 + 2 * c];
            uint32_t bl0 = *(const uint32_t*)&g_Wt_lo[n0 * DIM + kb + 2 * c];
            uint32_t bl1 = *(const uint32_t*)&g_Wt_lo[n0 * DIM + kb + 8 + 2 * c];
            #pragma unroll
            for (int i = 0; i < 2; i++) {
                mma16816(acc[i][j], ah[i], bh0, bh1);
                mma16816(acc[i][j], ah[i], bl0, bl1);
                mma16816(acc[i][j], al[i], bh0, bh1);
            }
        }
    }

    // store h as fp16 (half2 pairs)
    #pragma unroll
    for (int i = 0; i < 2; i++) {
        int r = row0 + wm * 32 + i * 16 + g;
        #pragma unroll
        for (int j = 0; j < 4; j++) {
            int ncol = wn * 32 + j * 8 + 2 * c;
            if (r < N)
                *(__half2*)&g_h[(size_t)r * DIM + ncol] = __floats2half2_rn(acc[i][j][0], acc[i][j][1]);
            if (r + 8 < N)
                *(__half2*)&g_h[(size_t)(r + 8) * DIM + ncol] = __floats2half2_rn(acc[i][j][2], acc[i][j][3]);
        }
    }
}

// ---------------- gather + bias + LayerNorm + GELU + residual (one warp per node) ----------------
__device__ __forceinline__ void fma_row(float4& acc, uint2 u, float n) {
    float2 f01 = __half22float2(*(__half2*)&u.x);
    float2 f23 = __half22float2(*(__half2*)&u.y);
    acc.x += f01.x * n;
    acc.y += f01.y * n;
    acc.z += f23.x * n;
    acc.w += f23.y * n;
}

__global__ __launch_bounds__(256) void gather_ln_kernel(
    const float4* __restrict__ x, float4* __restrict__ out,
    const float4* __restrict__ b, const float4* __restrict__ gamma,
    const float4* __restrict__ beta, int N)
{
    int w = (blockIdx.x * blockDim.x + threadIdx.x) >> 5;
    int lane = threadIdx.x & 31;
    if (w >= N) return;

    int s0 = g_off[w];
    int cnt = g_cnt[w];
    int end = s0 + cnt;

    float4 acc = b[lane];
    const uint2* hv = (const uint2*)g_h;   // 32 x uint2 (4 halfs) per row

    for (int e = s0; e < end; e += 4) {
        int e1 = e + 1 < end ? e + 1 : end - 1;
        int e2 = e + 2 < end ? e + 2 : end - 1;
        int e3 = e + 3 < end ? e + 3 : end - 1;
        int2 d0 = g_edges[e];
        int2 d1 = g_edges[e1];
        int2 d2 = g_edges[e2];
        int2 d3 = g_edges[e3];
        float n0 = __int_as_float(d0.y);
        float n1 = (e + 1 < end) ? __int_as_float(d1.y) : 0.0f;
        float n2 = (e + 2 < end) ? __int_as_float(d2.y) : 0.0f;
        float n3 = (e + 3 < end) ? __int_as_float(d3.y) : 0.0f;
        uint2 v0 = hv[(size_t)d0.x * 32 + lane];
        uint2 v1 = hv[(size_t)d1.x * 32 + lane];
        uint2 v2 = hv[(size_t)d2.x * 32 + lane];
        uint2 v3 = hv[(size_t)d3.x * 32 + lane];
        fma_row(acc, v0, n0);
        fma_row(acc, v1, n1);
        fma_row(acc, v2, n2);
        fma_row(acc, v3, n3);
    }

    float s = acc.x + acc.y + acc.z + acc.w;
    #pragma unroll
    for (int off = 16; off > 0; off >>= 1) s += __shfl_xor_sync(0xffffffffu, s, off);
    float mu = s * (1.0f / 128.0f);

    float dx = acc.x - mu, dy = acc.y - mu, dz = acc.z - mu, dw = acc.w - mu;
    float sq = dx * dx + dy * dy + dz * dz + dw * dw;
    #pragma unroll
    for (int off = 16; off > 0; off >>= 1) sq += __shfl_xor_sync(0xffffffffu, sq, off);
    float rinv = rsqrtf(sq * (1.0f / 128.0f) + 1e-5f);

    float4 gm = gamma[lane];
    float4 bt = beta[lane];
    float4 xv = __ldcs(&x[(size_t)w * 32 + lane]);

    float4 o;
    {
        float t = dx * rinv * gm.x + bt.x;
        o.x = xv.x + 0.5f * t * (1.0f + erff(t * 0.70710678118654752f));
        t = dy * rinv * gm.y + bt.y;
        o.y = xv.y + 0.5f * t * (1.0f + erff(t * 0.70710678118654752f));
        t = dz * rinv * gm.z + bt.z;
        o.z = xv.z + 0.5f * t * (1.0f + erff(t * 0.70710678118654752f));
        t = dw * rinv * gm.w + bt.w;
        o.w = xv.w + 0.5f * t * (1.0f + erff(t * 0.70710678118654752f));
    }
    __stcs(&out[(size_t)w * 32 + lane], o);
}

// ---------------- launch ----------------
extern "C" void kernel_launch(void* const* d_in, const int* in_sizes, int n_in,
                              void* d_out, int out_size) {
    const float* x = (const float*)d_in[0];
    const int* ei = (const int*)d_in[1];
    const float* ew = (const float*)d_in[2];
    const float* W = (const float*)d_in[3];
    const float* b = (const float*)d_in[4];
    const float* gamma = (const float*)d_in[5];
    const float* beta = (const float*)d_in[6];
    float* out = (float*)d_out;

    int N = in_sizes[0] / DIM;
    int E = in_sizes[1] / 2;   // edge_index delivered as int32 [2, E]

    static cudaStream_t s_side = nullptr;
    static cudaEvent_t ev_init = nullptr, ev_gemm = nullptr;
    if (!s_side) {
        cudaStreamCreateWithFlags(&s_side, cudaStreamNonBlocking);
        cudaEventCreateWithFlags(&ev_init, cudaEventDisableTiming);
        cudaEventCreateWithFlags(&ev_gemm, cudaEventDisableTiming);
    }

    // launch 1: init + W split (feeds both branches)
    initwsplit_kernel<<<(N + 255) / 256, 256>>>(W, N);
    cudaEventRecord(ev_init, 0);

    // launch 2 (side): GEMM, overlapped with the CSR build
    cudaStreamWaitEvent(s_side, ev_init, 0);
    gemm_kernel<<<(N + 63) / 64, 256, 0, s_side>>>(x, N);
    cudaEventRecord(ev_gemm, s_side);

    // launch 3 (main): fused persistent CSR build (deg -> dinv+scan -> fill)
    csr_kernel<<<CSR_BLOCKS, CSR_THREADS>>>(ei, ew, N, E);

    // launch 4 (main): fused gather + LN + GELU + residual (profiled slot)
    cudaStreamWaitEvent(0, ev_gemm, 0);
    gather_ln_kernel<<<(N + 7) / 8, 256>>>((const float4*)x, (float4*)out,
                                           (const float4*)b, (const float4*)gamma,
                                           (const float4*)beta, N);
}

// round 10
// speedup vs baseline: 1.0822x; 1.0822x over previous
#include <cuda_runtime.h>
#include <cuda_bf16.h>
#include <cuda_fp16.h>
#include <cstdint>

#define DIM 128
#define NMAX 100000
#define EMAX 600000
#define SCAN_B 1024

// ---------------- scratch (device globals; no allocations allowed) ----------------
__device__ float g_deg[NMAX];
__device__ float g_dinv[NMAX];
__device__ __align__(16) __half g_h[(size_t)NMAX * DIM];   // h in fp16 -> L2-resident
__device__ int  g_cnt[NMAX];
__device__ int  g_off[NMAX];
__device__ int  g_slot[EMAX];
__device__ int  g_blksum[128];
__device__ __align__(16) int2 g_edges[EMAX];   // (src row, norm bits) grouped by dst
__device__ __nv_bfloat16 g_Wt_hi[DIM * DIM];   // W transposed: [n][k], bf16 hi part
__device__ __nv_bfloat16 g_Wt_lo[DIM * DIM];   // bf16 lo part (residual)

// ---------------- launch 1: zero deg/cnt + split W ----------------
__global__ void initwsplit_kernel(const float* __restrict__ W, int N) {
    int i = blockIdx.x * blockDim.x + threadIdx.x;
    if (i < N) { g_deg[i] = 0.0f; g_cnt[i] = 0; }
    if (i < DIM * DIM) {
        int k = i >> 7, n = i & 127;
        float v = W[i];
        __nv_bfloat16 hi = __float2bfloat16(v);
        g_Wt_hi[n * DIM + k] = hi;
        g_Wt_lo[n * DIM + k] = __float2bfloat16(v - __bfloat162float(hi));
    }
}

// ---------------- degree + in-count + slot harvest ----------------
__global__ void deg_kernel(const int* __restrict__ col, const float* __restrict__ ew, int E) {
    int e = blockIdx.x * blockDim.x + threadIdx.x;
    if (e < E) {
        int c = col[e];
        atomicAdd(&g_deg[c], ew[e]);
        g_slot[e] = atomicAdd(&g_cnt[c], 1);
    }
}

// ---------------- scan1 (warp-shuffle) + fused dinv ----------------
__global__ __launch_bounds__(SCAN_B) void scan1_kernel(int N) {
    __shared__ int wsum[32];
    int t = threadIdx.x, i = blockIdx.x * SCAN_B + t;
    int lane = t & 31, wid = t >> 5;

    if (i < N) {
        float d = g_deg[i];
        g_dinv[i] = (d > 0.0f) ? rsqrtf(d) : 0.0f;
    }

    int v = (i < N) ? g_cnt[i] : 0;
    int s = v;
    #pragma unroll
    for (int o = 1; o < 32; o <<= 1) {
        int u = __shfl_up_sync(0xffffffffu, s, o);
        if (lane >= o) s += u;
    }
    if (lane == 31) wsum[wid] = s;
    __syncthreads();
    if (wid == 0) {
        int ws = wsum[lane];
        int p = ws;
        #pragma unroll
        for (int o = 1; o < 32; o <<= 1) {
            int u = __shfl_up_sync(0xffffffffu, p, o);
            if (lane >= o) p += u;
        }
        wsum[lane] = p - ws;   // exclusive warp offsets
    }
    __syncthreads();
    int excl = s - v + wsum[wid];
    if (i < N) g_off[i] = excl;
    if (t == SCAN_B - 1) g_blksum[blockIdx.x] = excl + v;
}

// ---------------- scan3: add chunk prefix (inline reduce over blksum) ----------------
__global__ __launch_bounds__(256) void scan3_kernel(int N) {
    __shared__ int sh[256];
    int t = threadIdx.x;
    int c = (blockIdx.x * 256) >> 10;          // 1024-chunk id of this block
    sh[t] = (t < c) ? g_blksum[t] : 0;         // c <= 98 < 256
    __syncthreads();
    #pragma unroll
    for (int o = 128; o > 0; o >>= 1) {
        if (t < o) sh[t] += sh[t + o];
        __syncthreads();
    }
    int prefix = sh[0];
    int i = blockIdx.x * 256 + t;
    if (i < N) g_off[i] += prefix;
}

// ---------------- fill CSR edge records (no atomics: slot precomputed) ----------------
__global__ void fill_kernel(const int* __restrict__ ei, const float* __restrict__ ew, int E) {
    int e = blockIdx.x * blockDim.x + threadIdx.x;
    if (e >= E) return;
    int r = ei[e];
    int c = ei[E + e];
    float nrm = g_dinv[r] * ew[e] * g_dinv[c];
    int p = g_off[c] + g_slot[e];
    g_edges[p] = make_int2(r, __float_as_int(nrm));
}

// ---------------- GEMM: h = x @ W  (bf16 3-term split on tensor cores) ----------------
__device__ __forceinline__ void mma16816(float* c, const uint32_t* a, uint32_t b0, uint32_t b1) {
    asm volatile(
        "mma.sync.aligned.m16n8k16.row.col.f32.bf16.bf16.f32 "
        "{%0,%1,%2,%3}, {%4,%5,%6,%7}, {%8,%9}, {%0,%1,%2,%3};"
        : "+f"(c[0]), "+f"(c[1]), "+f"(c[2]), "+f"(c[3])
        : "r"(a[0]), "r"(a[1]), "r"(a[2]), "r"(a[3]), "r"(b0), "r"(b1));
}

__device__ __forceinline__ uint32_t pack_bf16x2(float a, float b) {
    __nv_bfloat162 p = __floats2bfloat162_rn(a, b);
    return *(uint32_t*)&p;
}

#define LDA 136  // 128 + 8 bf16 pad -> conflict-free fragment loads

__global__ __launch_bounds__(256) void gemm_kernel(const float* __restrict__ x, int N) {
    __shared__ __nv_bfloat16 As_hi[64 * LDA];
    __shared__ __nv_bfloat16 As_lo[64 * LDA];

    const int tid = threadIdx.x;
    const int row0 = blockIdx.x * 64;

    // stage x tile -> bf16 hi/lo in smem, float4 loads + bf16x2 packed stores
    const float4* xv4 = (const float4*)x;
    #pragma unroll
    for (int idx = tid; idx < 64 * 32; idx += 256) {
        int r = idx >> 5, q = idx & 31;           // row, float4 column
        float4 v = make_float4(0.f, 0.f, 0.f, 0.f);
        if (row0 + r < N) v = __ldcs(&xv4[(size_t)(row0 + r) * 32 + q]);
        int k = q * 4;
        __nv_bfloat16 h0 = __float2bfloat16(v.x);
        __nv_bfloat16 h1 = __float2bfloat16(v.y);
        __nv_bfloat16 h2 = __float2bfloat16(v.z);
        __nv_bfloat16 h3 = __float2bfloat16(v.w);
        *(uint32_t*)&As_hi[r * LDA + k]     = pack_bf16x2(v.x, v.y) * 0 + (*(uint16_t*)&h0 | ((uint32_t)*(uint16_t*)&h1 << 16));
        *(uint32_t*)&As_hi[r * LDA + k + 2] = (*(uint16_t*)&h2 | ((uint32_t)*(uint16_t*)&h3 << 16));
        *(uint32_t*)&As_lo[r * LDA + k]     = pack_bf16x2(v.x - __bfloat162float(h0), v.y - __bfloat162float(h1));
        *(uint32_t*)&As_lo[r * LDA + k + 2] = pack_bf16x2(v.z - __bfloat162float(h2), v.w - __bfloat162float(h3));
    }
    __syncthreads();

    const int warp = tid >> 5, lane = tid & 31;
    const int wm = warp >> 2, wn = warp & 3;
    const int g = lane >> 2, c = lane & 3;

    float acc[2][4][4];
    #pragma unroll
    for (int i = 0; i < 2; i++)
        #pragma unroll
        for (int j = 0; j < 4; j++)
            #pragma unroll
            for (int q = 0; q < 4; q++) acc[i][j][q] = 0.0f;

    #pragma unroll
    for (int ks = 0; ks < 8; ks++) {
        const int kb = ks * 16;
        uint32_t ah[2][4], al[2][4];
        #pragma unroll
        for (int i = 0; i < 2; i++) {
            int r0 = wm * 32 + i * 16 + g;
            int col0 = kb + 2 * c;
            ah[i][0] = *(const uint32_t*)&As_hi[r0 * LDA + col0];
            ah[i][1] = *(const uint32_t*)&As_hi[(r0 + 8) * LDA + col0];
            ah[i][2] = *(const uint32_t*)&As_hi[r0 * LDA + col0 + 8];
            ah[i][3] = *(const uint32_t*)&As_hi[(r0 + 8) * LDA + col0 + 8];
            al[i][0] = *(const uint32_t*)&As_lo[r0 * LDA + col0];
            al[i][1] = *(const uint32_t*)&As_lo[(r0 + 8) * LDA + col0];
            al[i][2] = *(const uint32_t*)&As_lo[r0 * LDA + col0 + 8];
            al[i][3] = *(const uint32_t*)&As_lo[(r0 + 8) * LDA + col0 + 8];
        }
        #pragma unroll
        for (int j = 0; j < 4; j++) {
            int n0 = wn * 32 + j * 8 + g;
            uint32_t bh0 = *(const uint32_t*)&g_Wt_hi[n0 * DIM + kb + 2 * c];
            uint32_t bh1 = *(const uint32_t*)&g_Wt_hi[n0 * DIM + kb + 8 + 2 * c];
            uint32_t bl0 = *(const uint32_t*)&g_Wt_lo[n0 * DIM + kb + 2 * c];
            uint32_t bl1 = *(const uint32_t*)&g_Wt_lo[n0 * DIM + kb + 8 + 2 * c];
            #pragma unroll
            for (int i = 0; i < 2; i++) {
                mma16816(acc[i][j], ah[i], bh0, bh1);
                mma16816(acc[i][j], ah[i], bl0, bl1);
                mma16816(acc[i][j], al[i], bh0, bh1);
            }
        }
    }

    // store h as fp16 (half2 pairs)
    #pragma unroll
    for (int i = 0; i < 2; i++) {
        int r = row0 + wm * 32 + i * 16 + g;
        #pragma unroll
        for (int j = 0; j < 4; j++) {
            int ncol = wn * 32 + j * 8 + 2 * c;
            if (r < N)
                *(__half2*)&g_h[(size_t)r * DIM + ncol] = __floats2half2_rn(acc[i][j][0], acc[i][j][1]);
            if (r + 8 < N)
                *(__half2*)&g_h[(size_t)(r + 8) * DIM + ncol] = __floats2half2_rn(acc[i][j][2], acc[i][j][3]);
        }
    }
}

// ---------------- gather + bias + LayerNorm + GELU + residual (one warp per node) ----------------
__device__ __forceinline__ void fma_row(float4& acc, uint2 u, float n) {
    float2 f01 = __half22float2(*(__half2*)&u.x);
    float2 f23 = __half22float2(*(__half2*)&u.y);
    acc.x += f01.x * n;
    acc.y += f01.y * n;
    acc.z += f23.x * n;
    acc.w += f23.y * n;
}

__global__ __launch_bounds__(256) void gather_ln_kernel(
    const float4* __restrict__ x, float4* __restrict__ out,
    const float4* __restrict__ b, const float4* __restrict__ gamma,
    const float4* __restrict__ beta, int N)
{
    int w = (blockIdx.x * blockDim.x + threadIdx.x) >> 5;
    int lane = threadIdx.x & 31;
    if (w >= N) return;

    int s0 = g_off[w];
    int cnt = g_cnt[w];
    int end = s0 + cnt;

    float4 acc = b[lane];
    const uint2* hv = (const uint2*)g_h;   // 32 x uint2 (4 halfs) per row

    // clean 4-batches: no clamps, no selects
    int e = s0;
    int nfull = cnt & ~3;
    for (int stop = s0 + nfull; e < stop; e += 4) {
        int2 d0 = g_edges[e];
        int2 d1 = g_edges[e + 1];
        int2 d2 = g_edges[e + 2];
        int2 d3 = g_edges[e + 3];
        uint2 v0 = hv[(size_t)d0.x * 32 + lane];
        uint2 v1 = hv[(size_t)d1.x * 32 + lane];
        uint2 v2 = hv[(size_t)d2.x * 32 + lane];
        uint2 v3 = hv[(size_t)d3.x * 32 + lane];
        fma_row(acc, v0, __int_as_float(d0.y));
        fma_row(acc, v1, __int_as_float(d1.y));
        fma_row(acc, v2, __int_as_float(d2.y));
        fma_row(acc, v3, __int_as_float(d3.y));
    }
    // one clamped batch for the 1-3 edge tail
    if (e < end) {
        int e1 = e + 1 < end ? e + 1 : end - 1;
        int e2 = e + 2 < end ? e + 2 : end - 1;
        int2 d0 = g_edges[e];
        int2 d1 = g_edges[e1];
        int2 d2 = g_edges[e2];
        float n0 = __int_as_float(d0.y);
        float n1 = (e + 1 < end) ? __int_as_float(d1.y) : 0.0f;
        float n2 = (e + 2 < end) ? __int_as_float(d2.y) : 0.0f;
        uint2 v0 = hv[(size_t)d0.x * 32 + lane];
        uint2 v1 = hv[(size_t)d1.x * 32 + lane];
        uint2 v2 = hv[(size_t)d2.x * 32 + lane];
        fma_row(acc, v0, n0);
        fma_row(acc, v1, n1);
        fma_row(acc, v2, n2);
    }

    float s = acc.x + acc.y + acc.z + acc.w;
    #pragma unroll
    for (int off = 16; off > 0; off >>= 1) s += __shfl_xor_sync(0xffffffffu, s, off);
    float mu = s * (1.0f / 128.0f);

    float dx = acc.x - mu, dy = acc.y - mu, dz = acc.z - mu, dw = acc.w - mu;
    float sq = dx * dx + dy * dy + dz * dz + dw * dw;
    #pragma unroll
    for (int off = 16; off > 0; off >>= 1) sq += __shfl_xor_sync(0xffffffffu, sq, off);
    float rinv = rsqrtf(sq * (1.0f / 128.0f) + 1e-5f);

    float4 gm = gamma[lane];
    float4 bt = beta[lane];
    float4 xv = __ldcs(&x[(size_t)w * 32 + lane]);

    float4 o;
    {
        float t = dx * rinv * gm.x + bt.x;
        o.x = xv.x + 0.5f * t * (1.0f + erff(t * 0.70710678118654752f));
        t = dy * rinv * gm.y + bt.y;
        o.y = xv.y + 0.5f * t * (1.0f + erff(t * 0.70710678118654752f));
        t = dz * rinv * gm.z + bt.z;
        o.z = xv.z + 0.5f * t * (1.0f + erff(t * 0.70710678118654752f));
        t = dw * rinv * gm.w + bt.w;
        o.w = xv.w + 0.5f * t * (1.0f + erff(t * 0.70710678118654752f));
    }
    __stcs(&out[(size_t)w * 32 + lane], o);
}

// ---------------- launch ----------------
extern "C" void kernel_launch(void* const* d_in, const int* in_sizes, int n_in,
                              void* d_out, int out_size) {
    const float* x = (const float*)d_in[0];
    const int* ei = (const int*)d_in[1];
    const float* ew = (const float*)d_in[2];
    const float* W = (const float*)d_in[3];
    const float* b = (const float*)d_in[4];
    const float* gamma = (const float*)d_in[5];
    const float* beta = (const float*)d_in[6];
    float* out = (float*)d_out;

    int N = in_sizes[0] / DIM;
    int E = in_sizes[1] / 2;   // edge_index delivered as int32 [2, E]
    int nb = (N + SCAN_B - 1) / SCAN_B;

    static cudaStream_t s_side = nullptr;
    static cudaEvent_t ev_init = nullptr, ev_gemm = nullptr;
    if (!s_side) {
        cudaStreamCreateWithFlags(&s_side, cudaStreamNonBlocking);
        cudaEventCreateWithFlags(&ev_init, cudaEventDisableTiming);
        cudaEventCreateWithFlags(&ev_gemm, cudaEventDisableTiming);
    }

    // launch 1: init + W split (feeds both branches)
    initwsplit_kernel<<<(N + 255) / 256, 256>>>(W, N);
    cudaEventRecord(ev_init, 0);

    // side: GEMM overlapped with the CSR chain
    cudaStreamWaitEvent(s_side, ev_init, 0);
    gemm_kernel<<<(N + 63) / 64, 256, 0, s_side>>>(x, N);
    cudaEventRecord(ev_gemm, s_side);

    // main chain: deg(+slot) -> scan1(+dinv) -> scan3 -> fill
    deg_kernel<<<(E + 255) / 256, 256>>>(ei + E, ew, E);
    scan1_kernel<<<nb, SCAN_B>>>(N);
    scan3_kernel<<<(N + 255) / 256, 256>>>(N);
    fill_kernel<<<(E + 255) / 256, 256>>>(ei, ew, E);

    // join, then fused gather + LN + GELU + residual
    cudaStreamWaitEvent(0, ev_gemm, 0);
    gather_ln_kernel<<<(N + 7) / 8, 256>>>((const float4*)x, (float4*)out,
                                           (const float4*)b, (const float4*)gamma,
                                           (const float4*)beta, N);
}